// round 13
// baseline (speedup 1.0000x reference)
#include <cuda_runtime.h>
#include <cstdint>

#define N_NODES 50000
#define N_EDGES 800000

// ---------------- scratch (static device allocation) ---------------------------
__device__ float g_summed[N_NODES * 64];   // scatter-sum of hidden h (pre-W1b)
__device__ float g_counts[N_NODES];        // degree (float), written by scanC
__device__ float g_P[N_NODES * 64];        // x @ W1a[0:64,:]  (split-K partial)
__device__ int   g_histi[N_NODES];         // int degree histogram
__device__ int   g_cursor[N_NODES];        // exclusive-scan offsets (mutated by permute)
__device__ int   g_part[128];              // scan partials
__device__ int   g_srow[N_EDGES];          // sorted-by-row: row
__device__ int   g_scol[N_EDGES];          // sorted-by-row: col
__device__ int   g_seid[N_EDGES];          // sorted-by-row: original edge id

// ---------------- helpers -------------------------------------------------------
__device__ __forceinline__ uint32_t smem_u32(const void* p) {
    uint32_t a;
    asm("{ .reg .u64 t; cvta.to.shared.u64 t, %1; cvt.u32.u64 %0, t; }" : "=r"(a) : "l"(p));
    return a;
}
__device__ __forceinline__ uint32_t to_tf32(float f) {
    uint32_t r; asm("cvt.rna.tf32.f32 %0, %1;" : "=r"(r) : "f"(f)); return r;
}
__device__ __forceinline__ void red4(float* a, float4 v) {
    asm volatile("red.global.add.v4.f32 [%0], {%1,%2,%3,%4};"
                 :: "l"(a), "f"(v.x), "f"(v.y), "f"(v.z), "f"(v.w) : "memory");
}
__device__ __forceinline__ void barp(int id) {
    asm volatile("bar.sync %0, 64;" :: "r"(id) : "memory");
}
__device__ __forceinline__ void cp16(uint32_t dst, const void* src) {
    asm volatile("cp.async.cg.shared.global [%0], [%1], 16;" :: "r"(dst), "l"(src) : "memory");
}
__device__ __forceinline__ void cp_commit() {
    asm volatile("cp.async.commit_group;" ::: "memory");
}
template <int N> __device__ __forceinline__ void cp_wait() {
    asm volatile("cp.async.wait_group %0;" :: "n"(N) : "memory");
}
// m16n8k8 tf32 MMA (layouts as in prior rounds)
__device__ __forceinline__ void mma8(float d[4], const uint32_t a[4],
                                     uint32_t b0, uint32_t b1) {
    asm("mma.sync.aligned.m16n8k8.row.col.f32.tf32.tf32.f32 "
        "{%0,%1,%2,%3}, {%4,%5,%6,%7}, {%8,%9}, {%0,%1,%2,%3};"
        : "+f"(d[0]), "+f"(d[1]), "+f"(d[2]), "+f"(d[3])
        : "r"(a[0]), "r"(a[1]), "r"(a[2]), "r"(a[3]), "r"(b0), "r"(b1));
}

__device__ __forceinline__ bool sniff64(const void* ei) {
    const int* e32 = reinterpret_cast<const int*>(ei);
    return ((e32[1] | e32[3] | e32[5] | e32[7]) == 0);
}
__device__ __forceinline__ int load_ei(const void* ei, bool is64, size_t idx) {
    return is64 ? (int)reinterpret_cast<const long long*>(ei)[idx]
                : reinterpret_cast<const int*>(ei)[idx];
}

// ---------------- weight staging --------------------------------------------------
template <int KC, int NTHR>
__device__ __forceinline__ void stage_w_p4(uint4* sW, const float* __restrict__ W, int tid) {
    for (int i = tid; i < KC * 128; i += NTHR) {
        const int kc = i >> 7, nbp = (i >> 5) & 3, t = i & 31;
        const int k0 = kc * 8 + (t & 3);
        const int n0 = (2 * nbp) * 8 + (t >> 2), n1 = n0 + 8;
        uint4 fr;
        fr.x = to_tf32(W[k0 * 64 + n0]);
        fr.y = to_tf32(W[(k0 + 4) * 64 + n0]);
        fr.z = to_tf32(W[k0 * 64 + n1]);
        fr.w = to_tf32(W[(k0 + 4) * 64 + n1]);
        sW[i] = fr;
    }
}
template <int KC, int NTHR>
__device__ __forceinline__ void stage_w(uint2* sW, const float* __restrict__ W, int tid) {
    for (int i = tid; i < KC * 256; i += NTHR) {
        const int kc = i >> 8, nb = (i >> 5) & 7, t = i & 31;
        const int k0 = kc * 8 + (t & 3), n = nb * 8 + (t >> 2);
        uint2 fr;
        fr.x = to_tf32(W[k0 * 64 + n]);
        fr.y = to_tf32(W[(k0 + 4) * 64 + n]);
        sW[i] = fr;
    }
}

// ---------------- GEMM core (P/node): warp = 16 rows x 32 cols -----------------------
template <int KC>
__device__ __forceinline__ void gemm(const float* __restrict__ sIn, int lds,
                                     const uint2* __restrict__ sWf,
                                     int tg, int tc, int lane, int cg, float acc[4][4]) {
#pragma unroll
    for (int nb = 0; nb < 4; ++nb)
#pragma unroll
        for (int j = 0; j < 4; ++j) acc[nb][j] = 0.0f;
    const float* p0 = sIn + tg * lds;
#pragma unroll 4
    for (int kc = 0; kc < KC; ++kc) {
        const float* q = p0 + kc * 8 + tc;
        uint32_t a[4];
        a[0] = __float_as_uint(q[0]);
        a[1] = __float_as_uint(q[8 * lds]);
        a[2] = __float_as_uint(q[4]);
        a[3] = __float_as_uint(q[8 * lds + 4]);
#pragma unroll
        for (int nb = 0; nb < 4; ++nb) {
            const uint2 B = sWf[(kc * 8 + cg * 4 + nb) * 32 + lane];
            mma8(acc[nb], a, B.x, B.y);
        }
    }
}

// =====================================================================================
// SORT PIPELINE: zero -> hist -> scanA/B/C -> permute
// =====================================================================================
__global__ void zero_pass() {
    const int i = blockIdx.x * blockDim.x + threadIdx.x, s = gridDim.x * blockDim.x;
    const float4 z4 = make_float4(0.f, 0.f, 0.f, 0.f);
    for (int j = i; j < N_NODES * 16; j += s)
        reinterpret_cast<float4*>(g_summed)[j] = z4;
    for (int j = i; j < N_NODES; j += s) g_histi[j] = 0;
}

__global__ void hist_pass(const void* __restrict__ ei) {
    const bool is64 = sniff64(ei);
    const int i = blockIdx.x * blockDim.x + threadIdx.x, s = gridDim.x * blockDim.x;
    for (int e = i; e < N_EDGES; e += s)
        atomicAdd(&g_histi[load_ei(ei, is64, e)], 1);
}

#define SCAN_NB 98    // 98 * 512 = 50176 >= N_NODES
__global__ void scanA() {
    __shared__ int s[512];
    const int t = threadIdx.x, i = blockIdx.x * 512 + t;
    s[t] = (i < N_NODES) ? g_histi[i] : 0;
    __syncthreads();
    for (int o = 256; o > 0; o >>= 1) {
        if (t < o) s[t] += s[t + o];
        __syncthreads();
    }
    if (t == 0) g_part[blockIdx.x] = s[0];
}
__global__ void scanB() {
    int run = 0;
    for (int i = 0; i < SCAN_NB; ++i) { const int v = g_part[i]; g_part[i] = run; run += v; }
}
__global__ void scanC() {
    __shared__ int s[512];
    const int t = threadIdx.x, i = blockIdx.x * 512 + t;
    const int v = (i < N_NODES) ? g_histi[i] : 0;
    s[t] = v;
    __syncthreads();
    for (int o = 1; o < 512; o <<= 1) {
        const int x = s[t];
        const int y = (t >= o) ? s[t - o] : 0;
        __syncthreads();
        s[t] = x + y;
        __syncthreads();
    }
    if (i < N_NODES) {
        g_cursor[i] = g_part[blockIdx.x] + s[t] - v;   // exclusive offset
        g_counts[i] = (float)v;
    }
}

__global__ void permute_pass(const void* __restrict__ ei) {
    const bool is64 = sniff64(ei);
    const int i = blockIdx.x * blockDim.x + threadIdx.x, s = gridDim.x * blockDim.x;
    for (int e = i; e < N_EDGES; e += s) {
        const int r = load_ei(ei, is64, e);
        const int c = load_ei(ei, is64, (size_t)N_EDGES + e);
        const int pos = atomicAdd(&g_cursor[r], 1);
        g_srow[pos] = r; g_scol[pos] = c; g_seid[pos] = e;
    }
}

// =====================================================================================
// P PASS: g_P[n] = x[n] @ W1a[0:64,:]  (no bias; rna-converted inputs)
// =====================================================================================
#define PNT 768
#define PPAIRS 12
#define P_SMEM_F (4160 + PPAIRS * 1088)
#define P_SMEM_B (P_SMEM_F * 4)

__global__ void __launch_bounds__(PNT, 1)
p_pass(const float* __restrict__ x, const float* __restrict__ Wtop)
{
    extern __shared__ float sm[];
    uint2* sW = reinterpret_cast<uint2*>(sm);
    const int tid = threadIdx.x, lane = tid & 31;
    const int tg = lane >> 2, tc = lane & 3;
    const int pr = tid >> 6, pt = tid & 63, cg = (tid >> 5) & 1;

    float* sA = sm + 4160 + pr * 1088;

    stage_w<8, PNT>(sW, Wtop, tid);
    __syncthreads();

    const int NP = gridDim.x * PPAIRS;
    const int gp = blockIdx.x * PPAIRS + pr;
    const int ntiles = N_NODES / 16;   // exact

    for (int j = 0; gp + j * NP < ntiles; ++j) {
        const int base = (gp + j * NP) * 16;
#pragma unroll
        for (int it = 0; it < 4; ++it) {
            const int i = it * 64 + pt;
            const int row = i >> 4, q = i & 15;
            float4 v = reinterpret_cast<const float4*>(x)[(size_t)(base + row) * 16 + q];
            uint4 t4;
            t4.x = to_tf32(v.x); t4.y = to_tf32(v.y);
            t4.z = to_tf32(v.z); t4.w = to_tf32(v.w);
            *reinterpret_cast<uint4*>(sA + row * 68 + q * 4) = t4;
        }
        barp(pr + 1);

        float acc[4][4];
        gemm<8>(sA, 68, sW, tg, tc, lane, cg, acc);

#pragma unroll
        for (int nb = 0; nb < 4; ++nb) {
            const int col0 = cg * 32 + nb * 8 + 2 * tc;
            *reinterpret_cast<float2*>(g_P + (size_t)(base + tg) * 64 + col0) =
                make_float2(acc[nb][0], acc[nb][1]);
            *reinterpret_cast<float2*>(g_P + (size_t)(base + tg + 8) * 64 + col0) =
                make_float2(acc[nb][2], acc[nb][3]);
        }
        barp(pr + 1);
    }
}

// =====================================================================================
// EDGE PASS (sorted edges): h = relu(P[col] + ea[eid] @ W1a_bot + b1a);
// run-length segmented red-scatter (rows sorted within tile).
// 704 threads = 11 warp-pairs; tile = 32 sorted edges; warp = 32 rows (X=2) x 32 cols.
// =====================================================================================
#define ENT 704
#define EPAIRS 11
// pair floats: A(ea) 32x68 (2176) | PD 32x68 (2176) | ringR/C/E 3 x (4x32) ints (384)
#define E_PPF 4736
#define E_SMEM_F (4160 + EPAIRS * E_PPF)
#define E_SMEM_B (E_SMEM_F * 4)   // 225,024 B

__device__ __forceinline__ void load_idx_s(int tbase, int* rr, int* cc, int* ee, int pt) {
    if (pt < 32) {
        const int p = tbase + pt;
        rr[pt] = g_srow[p]; cc[pt] = g_scol[p]; ee[pt] = g_seid[p];
    }
}
__device__ __forceinline__ void gather_ea_s(const int* eids, const float* __restrict__ ea,
                                            uint32_t dst, int pt) {
#pragma unroll
    for (int it = 0; it < 8; ++it) {
        const int i = it * 64 + pt;
        const int row = i >> 4, q = i & 15;
        cp16(dst + (uint32_t)(row * 68 + q * 4) * 4,
             (const char*)ea + ((size_t)eids[row] * 64 + q * 4) * 4);
    }
}
__device__ __forceinline__ void gather_P(const int* cols, uint32_t dst, int pt) {
#pragma unroll
    for (int it = 0; it < 8; ++it) {
        const int i = it * 64 + pt;
        const int row = i >> 4, q = i & 15;
        cp16(dst + (uint32_t)(row * 68 + q * 4) * 4,
             (const char*)g_P + ((size_t)cols[row] * 64 + q * 4) * 4);
    }
}

__global__ void __launch_bounds__(ENT, 1)
edge_pass(const float* __restrict__ ea,
          const float* __restrict__ Wbot, const float* __restrict__ ba)
{
    extern __shared__ float sm[];
    uint4* sW  = reinterpret_cast<uint4*>(sm);
    float* sBa = sm + 4096;
    const int tid = threadIdx.x, lane = tid & 31;
    const int tg = lane >> 2, tc = lane & 3;
    const int pr = tid >> 6, pt = tid & 63, cg = (tid >> 5) & 1;

    float* sA  = sm + 4160 + pr * E_PPF;             // ea 32x68
    float* sPD = sA + 2176;                          // P / D in place, 32x68
    int* ringR = reinterpret_cast<int*>(sPD + 2176); // 4 x 32
    int* ringC = ringR + 128;
    int* ringE = ringC + 128;
    const uint32_t aU = smem_u32(sA), pU = smem_u32(sPD);

    stage_w_p4<8, ENT>(sW, Wbot, tid);
    if (tid < 64) sBa[tid] = ba[tid];
    __syncthreads();

    const int NP = gridDim.x * EPAIRS;
    const int gp = blockIdx.x * EPAIRS + pr;
    const int ntiles = N_EDGES / 32;       // exact: 25000

    // prologue: idx tiles 0,1; ea + P cp.async for tile 0 (two groups)
    load_idx_s(gp * 32, ringR, ringC, ringE, pt);
    if (gp + NP < ntiles)
        load_idx_s((gp + NP) * 32, ringR + 32, ringC + 32, ringE + 32, pt);
    barp(pr + 1);
    gather_ea_s(ringE, ea, aU, pt); cp_commit();
    gather_P(ringC, pU, pt);        cp_commit();

    for (int j = 0; gp + j * NP < ntiles; ++j) {
        const bool hasN = gp + (j + 1) * NP < ntiles;

        cp_wait<1>();   // ea arrived (P may still be in flight)
        barp(pr + 1);

        // ---- GEMM: [32x64](ea) @ [64x64], X=2 row groups, nb-pair packed B ----
        float acc[2][4][4];
#pragma unroll
        for (int g = 0; g < 2; ++g)
#pragma unroll
            for (int nb = 0; nb < 4; ++nb)
#pragma unroll
                for (int v = 0; v < 4; ++v) acc[g][nb][v] = 0.0f;
#pragma unroll
        for (int kc = 0; kc < 8; ++kc) {
            uint32_t a[2][4];
#pragma unroll
            for (int g = 0; g < 2; ++g) {
                const float* q = sA + (tg + 16 * g) * 68 + kc * 8 + tc;
                a[g][0] = __float_as_uint(q[0]);
                a[g][1] = __float_as_uint(q[8 * 68]);
                a[g][2] = __float_as_uint(q[4]);
                a[g][3] = __float_as_uint(q[8 * 68 + 4]);
            }
#pragma unroll
            for (int p = 0; p < 2; ++p) {
                const uint4 B = sW[(kc * 4 + cg * 2 + p) * 32 + lane];
                mma8(acc[0][2 * p],     a[0], B.x, B.y);
                mma8(acc[0][2 * p + 1], a[0], B.z, B.w);
                mma8(acc[1][2 * p],     a[1], B.x, B.y);
                mma8(acc[1][2 * p + 1], a[1], B.z, B.w);
            }
        }

        cp_wait<0>();   // P arrived
        barp(pr + 1);   // P visible pair-wide; A reads done -> ea refill safe

        // ---- ea refill for next tile NOW (ring idx loaded 2 ahead) ----
        if (hasN) {
            gather_ea_s(ringE + ((j + 1) & 3) * 32, ea, aU, pt);
            cp_commit();
        }
        if (gp + (j + 2) * NP < ntiles)
            load_idx_s((gp + (j + 2) * NP) * 32,
                       ringR + ((j + 2) & 3) * 32, ringC + ((j + 2) & 3) * 32,
                       ringE + ((j + 2) & 3) * 32, pt);

        // ---- epilogue: D = relu(acc + P + bias), IN PLACE over P ----
#pragma unroll
        for (int g = 0; g < 2; ++g) {
            const int rowa = tg + 16 * g, rowb = rowa + 8;
#pragma unroll
            for (int nb = 0; nb < 4; ++nb) {
                const int col0 = cg * 32 + nb * 8 + 2 * tc;
                const float2 bi = *reinterpret_cast<const float2*>(sBa + col0);
                float2* Pa = reinterpret_cast<float2*>(sPD + rowa * 68 + col0);
                float2* Pb = reinterpret_cast<float2*>(sPD + rowb * 68 + col0);
                const float2 va = *Pa, vb = *Pb;
                *Pa = make_float2(fmaxf(acc[g][nb][0] + va.x + bi.x, 0.0f),
                                  fmaxf(acc[g][nb][1] + va.y + bi.y, 0.0f));
                *Pb = make_float2(fmaxf(acc[g][nb][2] + vb.x + bi.x, 0.0f),
                                  fmaxf(acc[g][nb][3] + vb.y + bi.y, 0.0f));
            }
        }
        barp(pr + 1);   // D staged pair-wide

        // ---- segmented scatter: rows sorted within tile -> one red4 per run ----
        {
            const int* rows = ringR + (j & 3) * 32;
            const int rs = pt >> 4, q = pt & 15;
            const int r0 = rs * 8, r1 = r0 + 8;
            int r = r0;
            if (rs > 0) {
                const int prev = rows[r0 - 1];
                while (r < r1 && rows[r] == prev) ++r;   // skip continuation runs
            }
            while (r < r1) {
                const int node = rows[r];
                float4 s = *reinterpret_cast<const float4*>(sPD + r * 68 + q * 4);
                int rr = r + 1;
                while (rr < 32 && rows[rr] == node) {
                    const float4 v = *reinterpret_cast<const float4*>(sPD + rr * 68 + q * 4);
                    s.x += v.x; s.y += v.y; s.z += v.z; s.w += v.w;
                    ++rr;
                }
                red4(g_summed + (size_t)node * 64 + q * 4, s);
                r = rr;
            }
        }
        barp(pr + 1);   // scatter reads of PD done -> P refill safe

        if (hasN) { gather_P(ringC + ((j + 1) & 3) * 32, pU, pt); cp_commit(); }
    }
}

// =====================================================================================
// NODE PASS (fused agg+node):
//   agg = (g_summed/max(cnt,1)) @ W1b + (cnt>0 ? b1b : 0)       [inline, per tile]
//   out = relu([x || agg] @ W2a + b2a) @ W2b + b2b
// =====================================================================================
#define NNT 768
#define NPAIRS 12
#define N_SMEM_F (16576 + NPAIRS * 3216)
#define N_SMEM_B (N_SMEM_F * 4)   // 220,672 B

__global__ void __launch_bounds__(NNT, 1)
node_pass(const float* __restrict__ x,
          const float* __restrict__ W1b, const float* __restrict__ b1b,
          const float* __restrict__ W2a, const float* __restrict__ b2a,
          const float* __restrict__ W2b, const float* __restrict__ b2b,
          float* __restrict__ outp)
{
    extern __shared__ float sm[];
    uint2* sW1b = reinterpret_cast<uint2*>(sm);
    uint2* sW2a = reinterpret_cast<uint2*>(sm + 4096);
    uint2* sW2b = reinterpret_cast<uint2*>(sm + 12288);
    float* sB1b = sm + 16384;
    float* sB2a = sm + 16448;
    float* sB2b = sm + 16512;
    const int tid = threadIdx.x, lane = tid & 31;
    const int tg = lane >> 2, tc = lane & 3;
    const int pr = tid >> 6, pt = tid & 63, cg = (tid >> 5) & 1;

    float* sA   = sm + 16576 + pr * 3216;   // 16 x 132
    float* sG   = sA + 2112;                // 16 x 68; sH overlays after consumption
    float* sCnt = sG + 1088;                // 16
    float* sH   = sG;

    stage_w<8, NNT>(sW1b, W1b, tid);
    stage_w<16, NNT>(sW2a, W2a, tid);
    stage_w<8, NNT>(sW2b, W2b, tid);
    if (tid < 64) { sB1b[tid] = b1b[tid]; sB2a[tid] = b2a[tid]; sB2b[tid] = b2b[tid]; }
    __syncthreads();

    const int NP = gridDim.x * NPAIRS;
    const int gp = blockIdx.x * NPAIRS + pr;
    const int ntiles = N_NODES / 16;   // exact

    for (int j = 0; gp + j * NP < ntiles; ++j) {
        const int base = (gp + j * NP) * 16;

#pragma unroll
        for (int it = 0; it < 4; ++it) {
            const int i = it * 64 + pt;
            const int row = i >> 4, q = i & 15;
            const int n = base + row;
            *reinterpret_cast<float4*>(sA + row * 132 + q * 4) =
                reinterpret_cast<const float4*>(x)[(size_t)n * 16 + q];
            const float cnt = g_counts[n];
            const float s = 1.0f / fmaxf(cnt, 1.0f);
            float4 v = reinterpret_cast<const float4*>(g_summed)[(size_t)n * 16 + q];
            v.x *= s; v.y *= s; v.z *= s; v.w *= s;
            *reinterpret_cast<float4*>(sG + row * 68 + q * 4) = v;
            sCnt[row] = cnt;
        }
        barp(pr + 1);

        float accA[4][4];
        gemm<8>(sG, 68, sW1b, tg, tc, lane, cg, accA);

        const float ca = sCnt[tg], cb = sCnt[tg + 8];
#pragma unroll
        for (int nb = 0; nb < 4; ++nb) {
            const int col0 = cg * 32 + nb * 8 + 2 * tc;
            const float2 bi = *reinterpret_cast<const float2*>(sB1b + col0);
            *reinterpret_cast<float2*>(sA + tg * 132 + 64 + col0) =
                make_float2(accA[nb][0] + (ca > 0.0f ? bi.x : 0.0f),
                            accA[nb][1] + (ca > 0.0f ? bi.y : 0.0f));
            *reinterpret_cast<float2*>(sA + (tg + 8) * 132 + 64 + col0) =
                make_float2(accA[nb][2] + (cb > 0.0f ? bi.x : 0.0f),
                            accA[nb][3] + (cb > 0.0f ? bi.y : 0.0f));
        }
        barp(pr + 1);

        float acc[4][4];
        gemm<16>(sA, 132, sW2a, tg, tc, lane, cg, acc);

#pragma unroll
        for (int nb = 0; nb < 4; ++nb) {
            const int col0 = cg * 32 + nb * 8 + 2 * tc;
            const float2 bi = *reinterpret_cast<const float2*>(sB2a + col0);
            *reinterpret_cast<float2*>(sH + tg * 68 + col0) =
                make_float2(fmaxf(acc[nb][0] + bi.x, 0.0f), fmaxf(acc[nb][1] + bi.y, 0.0f));
            *reinterpret_cast<float2*>(sH + (tg + 8) * 68 + col0) =
                make_float2(fmaxf(acc[nb][2] + bi.x, 0.0f), fmaxf(acc[nb][3] + bi.y, 0.0f));
        }
        barp(pr + 1);

        float acc2[4][4];
        gemm<8>(sH, 68, sW2b, tg, tc, lane, cg, acc2);

#pragma unroll
        for (int nb = 0; nb < 4; ++nb) {
            const int col0 = cg * 32 + nb * 8 + 2 * tc;
            const float2 bi = *reinterpret_cast<const float2*>(sB2b + col0);
            *reinterpret_cast<float2*>(outp + (size_t)(base + tg) * 64 + col0) =
                make_float2(acc2[nb][0] + bi.x, acc2[nb][1] + bi.y);
            *reinterpret_cast<float2*>(outp + (size_t)(base + tg + 8) * 64 + col0) =
                make_float2(acc2[nb][2] + bi.x, acc2[nb][3] + bi.y);
        }
        barp(pr + 1);
    }
}

// ---------------- launch ----------------------------------------------------------------
extern "C" void kernel_launch(void* const* d_in, const int* in_sizes, int n_in,
                              void* d_out, int out_size) {
    const float* x   = reinterpret_cast<const float*>(d_in[0]);
    const void*  ei  = d_in[1];
    const float* ea  = reinterpret_cast<const float*>(d_in[2]);
    const float* W1a = reinterpret_cast<const float*>(d_in[5]);
    const float* b1a = reinterpret_cast<const float*>(d_in[6]);
    const float* W1b = reinterpret_cast<const float*>(d_in[7]);
    const float* b1b = reinterpret_cast<const float*>(d_in[8]);
    const float* W2a = reinterpret_cast<const float*>(d_in[9]);
    const float* b2a = reinterpret_cast<const float*>(d_in[10]);
    const float* W2b = reinterpret_cast<const float*>(d_in[11]);
    const float* b2b = reinterpret_cast<const float*>(d_in[12]);
    float* out = reinterpret_cast<float*>(d_out);

    cudaFuncSetAttribute(p_pass,    cudaFuncAttributeMaxDynamicSharedMemorySize, P_SMEM_B);
    cudaFuncSetAttribute(edge_pass, cudaFuncAttributeMaxDynamicSharedMemorySize, E_SMEM_B);
    cudaFuncSetAttribute(node_pass, cudaFuncAttributeMaxDynamicSharedMemorySize, N_SMEM_B);

    zero_pass<<<148, 256>>>();
    hist_pass<<<148, 256>>>(ei);
    scanA<<<SCAN_NB, 512>>>();
    scanB<<<1, 1>>>();
    scanC<<<SCAN_NB, 512>>>();
    permute_pass<<<148, 256>>>(ei);
    p_pass<<<148, PNT, P_SMEM_B>>>(x, W1a);
    edge_pass<<<148, ENT, E_SMEM_B>>>(ea, W1a + 64 * 64, b1a);
    node_pass<<<148, NNT, N_SMEM_B>>>(x, W1b, b1b, W2a, b2a, W2b, b2b, out);
}

// round 14
// speedup vs baseline: 1.3250x; 1.3250x over previous
#include <cuda_runtime.h>
#include <cstdint>

#define N_NODES 50000
#define N_EDGES 800000

// ---------------- scratch (static device allocation) ---------------------------
__device__ float g_summed[N_NODES * 64];   // scatter-sum of hidden h (pre-W1b)
__device__ float g_counts[N_NODES];
__device__ float g_P[N_NODES * 64];        // x @ W1a[0:64,:]  (split-K partial)

// ---------------- helpers -------------------------------------------------------
__device__ __forceinline__ uint32_t smem_u32(const void* p) {
    uint32_t a;
    asm("{ .reg .u64 t; cvta.to.shared.u64 t, %1; cvt.u32.u64 %0, t; }" : "=r"(a) : "l"(p));
    return a;
}
__device__ __forceinline__ uint32_t to_tf32(float f) {
    uint32_t r; asm("cvt.rna.tf32.f32 %0, %1;" : "=r"(r) : "f"(f)); return r;
}
__device__ __forceinline__ void red4(float* a, float4 v) {
    asm volatile("red.global.add.v4.f32 [%0], {%1,%2,%3,%4};"
                 :: "l"(a), "f"(v.x), "f"(v.y), "f"(v.z), "f"(v.w) : "memory");
}
__device__ __forceinline__ void barp(int id) {
    asm volatile("bar.sync %0, 64;" :: "r"(id) : "memory");
}
__device__ __forceinline__ void cp16(uint32_t dst, const void* src) {
    asm volatile("cp.async.cg.shared.global [%0], [%1], 16;" :: "r"(dst), "l"(src) : "memory");
}
__device__ __forceinline__ void cp_commit() {
    asm volatile("cp.async.commit_group;" ::: "memory");
}
template <int N> __device__ __forceinline__ void cp_wait() {
    asm volatile("cp.async.wait_group %0;" :: "n"(N) : "memory");
}
// m16n8k8 tf32 MMA. g = lane>>2, c = lane&3:
//   A: a0=A[g][c] a1=A[g+8][c] a2=A[g][c+4] a3=A[g+8][c+4]
//   B: b0=B[c][n] b1=B[c+4][n]  (n = lane>>2)
//   D: d0=D[g][2c] d1=D[g][2c+1] d2=D[g+8][2c] d3=D[g+8][2c+1]
__device__ __forceinline__ void mma8(float d[4], const uint32_t a[4],
                                     uint32_t b0, uint32_t b1) {
    asm("mma.sync.aligned.m16n8k8.row.col.f32.tf32.tf32.f32 "
        "{%0,%1,%2,%3}, {%4,%5,%6,%7}, {%8,%9}, {%0,%1,%2,%3};"
        : "+f"(d[0]), "+f"(d[1]), "+f"(d[2]), "+f"(d[3])
        : "r"(a[0]), "r"(a[1]), "r"(a[2]), "r"(a[3]), "r"(b0), "r"(b1));
}

// ---------------- weight staging --------------------------------------------------
// (a) nb-pair packed, single tf32 (edge): sW[(kc*4+nbp)*32+lane] =
//     {b0(nb=2nbp), b1(nb=2nbp), b0(nb=2nbp+1), b1(nb=2nbp+1)}
template <int KC, int NTHR>
__device__ __forceinline__ void stage_w_p4(uint4* sW, const float* __restrict__ W, int tid) {
    for (int i = tid; i < KC * 128; i += NTHR) {
        const int kc = i >> 7, nbp = (i >> 5) & 3, t = i & 31;
        const int k0 = kc * 8 + (t & 3);
        const int n0 = (2 * nbp) * 8 + (t >> 2), n1 = n0 + 8;
        uint4 fr;
        fr.x = to_tf32(W[k0 * 64 + n0]);
        fr.y = to_tf32(W[(k0 + 4) * 64 + n0]);
        fr.z = to_tf32(W[k0 * 64 + n1]);
        fr.w = to_tf32(W[(k0 + 4) * 64 + n1]);
        sW[i] = fr;
    }
}
// (b) plain single tf32 (P/node): sW[(kc*8+nb)*32 + lane] = {b0, b1}
template <int KC, int NTHR>
__device__ __forceinline__ void stage_w(uint2* sW, const float* __restrict__ W, int tid) {
    for (int i = tid; i < KC * 256; i += NTHR) {
        const int kc = i >> 8, nb = (i >> 5) & 7, t = i & 31;
        const int k0 = kc * 8 + (t & 3), n = nb * 8 + (t >> 2);
        uint2 fr;
        fr.x = to_tf32(W[k0 * 64 + n]);
        fr.y = to_tf32(W[(k0 + 4) * 64 + n]);
        sW[i] = fr;
    }
}

// ---------------- GEMM core (P/node): warp = 16 rows x 32 cols -----------------------
template <int KC>
__device__ __forceinline__ void gemm(const float* __restrict__ sIn, int lds,
                                     const uint2* __restrict__ sWf,
                                     int tg, int tc, int lane, int cg, float acc[4][4]) {
#pragma unroll
    for (int nb = 0; nb < 4; ++nb)
#pragma unroll
        for (int j = 0; j < 4; ++j) acc[nb][j] = 0.0f;
    const float* p0 = sIn + tg * lds;
#pragma unroll 4
    for (int kc = 0; kc < KC; ++kc) {
        const float* q = p0 + kc * 8 + tc;
        uint32_t a[4];
        a[0] = __float_as_uint(q[0]);
        a[1] = __float_as_uint(q[8 * lds]);
        a[2] = __float_as_uint(q[4]);
        a[3] = __float_as_uint(q[8 * lds + 4]);
#pragma unroll
        for (int nb = 0; nb < 4; ++nb) {
            const uint2 B = sWf[(kc * 8 + cg * 4 + nb) * 32 + lane];
            mma8(acc[nb], a, B.x, B.y);
        }
    }
}

// =====================================================================================
// P PASS: zero scratch + g_P[n] = x[n] @ W1a[0:64,:]  (no bias; rna-converted inputs)
// =====================================================================================
#define PNT 768
#define PPAIRS 12
#define P_SMEM_F (4160 + PPAIRS * 1088)
#define P_SMEM_B (P_SMEM_F * 4)

__global__ void __launch_bounds__(PNT, 1)
p_pass(const float* __restrict__ x, const float* __restrict__ Wtop)
{
    extern __shared__ float sm[];
    uint2* sW = reinterpret_cast<uint2*>(sm);
    const int tid = threadIdx.x, lane = tid & 31;
    const int tg = lane >> 2, tc = lane & 3;
    const int pr = tid >> 6, pt = tid & 63, cg = (tid >> 5) & 1;

    float* sA = sm + 4160 + pr * 1088;

    // ---- zero scratch (replaces host-side memsets; before edge_pass launch) ----
    {
        const int gt = blockIdx.x * PNT + tid, gs = gridDim.x * PNT;
        const float4 z4 = make_float4(0.f, 0.f, 0.f, 0.f);
        for (int i = gt; i < N_NODES * 16; i += gs)
            reinterpret_cast<float4*>(g_summed)[i] = z4;
        for (int i = gt; i < N_NODES; i += gs) g_counts[i] = 0.0f;
    }

    stage_w<8, PNT>(sW, Wtop, tid);
    __syncthreads();

    const int NP = gridDim.x * PPAIRS;
    const int gp = blockIdx.x * PPAIRS + pr;
    const int ntiles = N_NODES / 16;   // exact

    for (int j = 0; gp + j * NP < ntiles; ++j) {
        const int base = (gp + j * NP) * 16;
#pragma unroll
        for (int it = 0; it < 4; ++it) {
            const int i = it * 64 + pt;          // [0, 256)
            const int row = i >> 4, q = i & 15;
            float4 v = reinterpret_cast<const float4*>(x)[(size_t)(base + row) * 16 + q];
            uint4 t4;
            t4.x = to_tf32(v.x); t4.y = to_tf32(v.y);
            t4.z = to_tf32(v.z); t4.w = to_tf32(v.w);
            *reinterpret_cast<uint4*>(sA + row * 68 + q * 4) = t4;
        }
        barp(pr + 1);

        float acc[4][4];
        gemm<8>(sA, 68, sW, tg, tc, lane, cg, acc);

#pragma unroll
        for (int nb = 0; nb < 4; ++nb) {
            const int col0 = cg * 32 + nb * 8 + 2 * tc;
            *reinterpret_cast<float2*>(g_P + (size_t)(base + tg) * 64 + col0) =
                make_float2(acc[nb][0], acc[nb][1]);
            *reinterpret_cast<float2*>(g_P + (size_t)(base + tg + 8) * 64 + col0) =
                make_float2(acc[nb][2], acc[nb][3]);
        }
        barp(pr + 1);   // sA reuse safe
    }
}

// =====================================================================================
// EDGE PASS: h = relu(P[col] + ea @ W1a_bot + b1a); coherent red-scatter h.
// 704 threads = 11 warp-pairs; tile = 32 rows; warp = 32 rows (X=2) x 32 cols.
// ea -> A buffer (pair-shared); P -> PD buffer, transformed IN PLACE into D.
// PD is cg-PARTITIONED: warp cg only ever touches cols [32cg, 32cg+32), so the
// D-staged and post-scatter hazards are intra-warp -> __syncwarp, not bar.sync.
// =====================================================================================
#define ENT 704
#define EPAIRS 11
// smem floats: W1bot nb-packed frags 4096 (16KB) | ba 64 | pairs at 4160, stride 4608:
//   A(ea) 32x68 (2176) | PD 32x68 (2176) | ringRow 4x32 | ringCol 4x32
#define E_PPF 4608
#define E_SMEM_F (4160 + EPAIRS * E_PPF)
#define E_SMEM_B (E_SMEM_F * 4)   // 219,392 B

__device__ __forceinline__ void load_idx_e(const void* ei, bool is64, int tbase,
                                           int* rs, int* cs, int pt) {
    if (pt < 32) {
        const int ge = tbase + pt;
        int r, c;
        if (is64) {
            const long long* e64 = reinterpret_cast<const long long*>(ei);
            r = (int)e64[ge]; c = (int)e64[N_EDGES + ge];
        } else {
            const int* e32 = reinterpret_cast<const int*>(ei);
            r = e32[ge]; c = e32[N_EDGES + ge];
        }
        atomicAdd(&g_counts[r], 1.0f);
        rs[pt] = r; cs[pt] = c;
    }
}

__device__ __forceinline__ void gather_ea(int base, const float* __restrict__ ea,
                                          uint32_t dst, int pt) {
#pragma unroll
    for (int it = 0; it < 8; ++it) {
        const int i = it * 64 + pt;          // [0, 512)
        const int row = i >> 4, q = i & 15;  // 32 rows x 16 16B-chunks
        cp16(dst + (uint32_t)(row * 68 + q * 4) * 4,
             (const char*)ea + ((size_t)(base + row) * 64 + q * 4) * 4);
    }
}
// warp-half P gather: warp cg loads only its own 32-col half of every row
__device__ __forceinline__ void gather_P_half(const int* cols, uint32_t dst,
                                              int lane, int cg) {
#pragma unroll
    for (int it = 0; it < 8; ++it) {
        const int i = it * 32 + lane;        // [0, 256)
        const int row = i >> 3, q = (i & 7) + cg * 8;
        cp16(dst + (uint32_t)(row * 68 + q * 4) * 4,
             (const char*)g_P + ((size_t)cols[row] * 64 + q * 4) * 4);
    }
}

__global__ void __launch_bounds__(ENT, 1)
edge_pass(const void* __restrict__ ei, const float* __restrict__ ea,
          const float* __restrict__ Wbot, const float* __restrict__ ba)
{
    extern __shared__ float sm[];
    uint4* sW  = reinterpret_cast<uint4*>(sm);
    float* sBa = sm + 4096;
    const int tid = threadIdx.x, lane = tid & 31;
    const int tg = lane >> 2, tc = lane & 3;
    const int pr = tid >> 6, pt = tid & 63, cg = (tid >> 5) & 1;

    float* sA  = sm + 4160 + pr * E_PPF;             // ea 32x68
    float* sPD = sA + 2176;                          // P / D in place, 32x68
    int* ringR = reinterpret_cast<int*>(sPD + 2176); // 4 x 32
    int* ringC = ringR + 128;                        // 4 x 32
    const uint32_t aU = smem_u32(sA), pU = smem_u32(sPD);

    stage_w_p4<8, ENT>(sW, Wbot, tid);
    if (tid < 64) sBa[tid] = ba[tid];
    __syncthreads();

    // dtype sniff: int64 edge_index has zero high words for small nonneg values
    const int* e32s = reinterpret_cast<const int*>(ei);
    const bool is64 = ((e32s[1] | e32s[3] | e32s[5] | e32s[7]) == 0);

    const int NP = gridDim.x * EPAIRS;
    const int gp = blockIdx.x * EPAIRS + pr;
    const int ntiles = N_EDGES / 32;       // exact: 25000

    // prologue: idx tiles 0,1; ea + P cp.async for tile 0 (two groups)
    load_idx_e(ei, is64, gp * 32, ringR, ringC, pt);
    if (gp + NP < ntiles)
        load_idx_e(ei, is64, (gp + NP) * 32, ringR + 32, ringC + 32, pt);
    barp(pr + 1);
    gather_ea(gp * 32, ea, aU, pt);       cp_commit();
    gather_P_half(ringC, pU, lane, cg);   cp_commit();

    for (int j = 0; gp + j * NP < ntiles; ++j) {
        const bool hasN = gp + (j + 1) * NP < ntiles;

        cp_wait<1>();   // ea arrived (P may still be in flight)
        barp(pr + 1);

        // ---- GEMM: [32x64](ea) @ [64x64], X=2 row groups, nb-pair packed B ----
        float acc[2][4][4];
#pragma unroll
        for (int g = 0; g < 2; ++g)
#pragma unroll
            for (int nb = 0; nb < 4; ++nb)
#pragma unroll
                for (int v = 0; v < 4; ++v) acc[g][nb][v] = 0.0f;
#pragma unroll
        for (int kc = 0; kc < 8; ++kc) {
            uint32_t a[2][4];
#pragma unroll
            for (int g = 0; g < 2; ++g) {
                const float* q = sA + (tg + 16 * g) * 68 + kc * 8 + tc;
                a[g][0] = __float_as_uint(q[0]);
                a[g][1] = __float_as_uint(q[8 * 68]);
                a[g][2] = __float_as_uint(q[4]);
                a[g][3] = __float_as_uint(q[8 * 68 + 4]);
            }
#pragma unroll
            for (int p = 0; p < 2; ++p) {
                const uint4 B = sW[(kc * 4 + cg * 2 + p) * 32 + lane];
                mma8(acc[0][2 * p],     a[0], B.x, B.y);
                mma8(acc[0][2 * p + 1], a[0], B.z, B.w);
                mma8(acc[1][2 * p],     a[1], B.x, B.y);
                mma8(acc[1][2 * p + 1], a[1], B.z, B.w);
            }
        }

        cp_wait<0>();   // P arrived (this warp's half)
        barp(pr + 1);   // A reads done both warps -> ea refill safe

        // ---- ea refill for next tile NOW (overlaps epilogue + scatter) ----
        if (hasN) { gather_ea((gp + (j + 1) * NP) * 32, ea, aU, pt); cp_commit(); }
        if (gp + (j + 2) * NP < ntiles)
            load_idx_e(ei, is64, (gp + (j + 2) * NP) * 32,
                       ringR + ((j + 2) & 3) * 32, ringC + ((j + 2) & 3) * 32, pt);

        // ---- epilogue: D = relu(acc + P + bias), IN PLACE over P (own cg half) ----
#pragma unroll
        for (int g = 0; g < 2; ++g) {
            const int rowa = tg + 16 * g, rowb = rowa + 8;
#pragma unroll
            for (int nb = 0; nb < 4; ++nb) {
                const int col0 = cg * 32 + nb * 8 + 2 * tc;
                const float2 bi = *reinterpret_cast<const float2*>(sBa + col0);
                float2* Pa = reinterpret_cast<float2*>(sPD + rowa * 68 + col0);
                float2* Pb = reinterpret_cast<float2*>(sPD + rowb * 68 + col0);
                const float2 va = *Pa, vb = *Pb;
                *Pa = make_float2(fmaxf(acc[g][nb][0] + va.x + bi.x, 0.0f),
                                  fmaxf(acc[g][nb][1] + va.y + bi.y, 0.0f));
                *Pb = make_float2(fmaxf(acc[g][nb][2] + vb.x + bi.x, 0.0f),
                                  fmaxf(acc[g][nb][3] + vb.y + bi.y, 0.0f));
            }
        }
        __syncwarp();   // D staged: intra-warp only (PD is cg-partitioned)

        // ---- coherent scatter over own cg half: warp instr = 4 rows x 128B = 4 lines
        const int* rows = ringR + (j & 3) * 32;
#pragma unroll
        for (int it = 0; it < 8; ++it) {
            const int i = it * 32 + lane;   // [0, 256)
            const int row = i >> 3, q = (i & 7) + cg * 8;
            const float4 v = *reinterpret_cast<const float4*>(sPD + row * 68 + q * 4);
            red4(g_summed + (size_t)rows[row] * 64 + q * 4, v);
        }
        __syncwarp();   // scatter reads of own half done -> P refill safe

        if (hasN) { gather_P_half(ringC + ((j + 1) & 3) * 32, pU, lane, cg); cp_commit(); }
    }
}

// =====================================================================================
// NODE PASS (fused agg+node):
//   agg = (g_summed/max(cnt,1)) @ W1b + (cnt>0 ? b1b : 0)       [inline, per tile]
//   out = relu([x || agg] @ W2a + b2a) @ W2b + b2b
// =====================================================================================
#define NNT 768
#define NPAIRS 12
#define N_SMEM_F (16576 + NPAIRS * 3216)
#define N_SMEM_B (N_SMEM_F * 4)   // 220,672 B

__global__ void __launch_bounds__(NNT, 1)
node_pass(const float* __restrict__ x,
          const float* __restrict__ W1b, const float* __restrict__ b1b,
          const float* __restrict__ W2a, const float* __restrict__ b2a,
          const float* __restrict__ W2b, const float* __restrict__ b2b,
          float* __restrict__ outp)
{
    extern __shared__ float sm[];
    uint2* sW1b = reinterpret_cast<uint2*>(sm);
    uint2* sW2a = reinterpret_cast<uint2*>(sm + 4096);
    uint2* sW2b = reinterpret_cast<uint2*>(sm + 12288);
    float* sB1b = sm + 16384;
    float* sB2a = sm + 16448;
    float* sB2b = sm + 16512;
    const int tid = threadIdx.x, lane = tid & 31;
    const int tg = lane >> 2, tc = lane & 3;
    const int pr = tid >> 6, pt = tid & 63, cg = (tid >> 5) & 1;

    float* sA   = sm + 16576 + pr * 3216;   // 16 x 132
    float* sG   = sA + 2112;                // 16 x 68; sH overlays after consumption
    float* sCnt = sG + 1088;                // 16
    float* sH   = sG;

    stage_w<8, NNT>(sW1b, W1b, tid);
    stage_w<16, NNT>(sW2a, W2a, tid);
    stage_w<8, NNT>(sW2b, W2b, tid);
    if (tid < 64) { sB1b[tid] = b1b[tid]; sB2a[tid] = b2a[tid]; sB2b[tid] = b2b[tid]; }
    __syncthreads();

    const int NP = gridDim.x * NPAIRS;
    const int gp = blockIdx.x * NPAIRS + pr;
    const int ntiles = N_NODES / 16;   // exact

    for (int j = 0; gp + j * NP < ntiles; ++j) {
        const int base = (gp + j * NP) * 16;

#pragma unroll
        for (int it = 0; it < 4; ++it) {
            const int i = it * 64 + pt;
            const int row = i >> 4, q = i & 15;
            const int n = base + row;
            *reinterpret_cast<float4*>(sA + row * 132 + q * 4) =
                reinterpret_cast<const float4*>(x)[(size_t)n * 16 + q];
            const float cnt = g_counts[n];
            const float s = 1.0f / fmaxf(cnt, 1.0f);
            float4 v = reinterpret_cast<const float4*>(g_summed)[(size_t)n * 16 + q];
            v.x *= s; v.y *= s; v.z *= s; v.w *= s;
            *reinterpret_cast<float4*>(sG + row * 68 + q * 4) = v;
            sCnt[row] = cnt;
        }
        barp(pr + 1);

        float accA[4][4];
        gemm<8>(sG, 68, sW1b, tg, tc, lane, cg, accA);

        const float ca = sCnt[tg], cb = sCnt[tg + 8];
#pragma unroll
        for (int nb = 0; nb < 4; ++nb) {
            const int col0 = cg * 32 + nb * 8 + 2 * tc;
            const float2 bi = *reinterpret_cast<const float2*>(sB1b + col0);
            *reinterpret_cast<float2*>(sA + tg * 132 + 64 + col0) =
                make_float2(accA[nb][0] + (ca > 0.0f ? bi.x : 0.0f),
                            accA[nb][1] + (ca > 0.0f ? bi.y : 0.0f));
            *reinterpret_cast<float2*>(sA + (tg + 8) * 132 + 64 + col0) =
                make_float2(accA[nb][2] + (cb > 0.0f ? bi.x : 0.0f),
                            accA[nb][3] + (cb > 0.0f ? bi.y : 0.0f));
        }
        barp(pr + 1);   // sA complete; sG consumed (sH overlay safe)

        float acc[4][4];
        gemm<16>(sA, 132, sW2a, tg, tc, lane, cg, acc);

#pragma unroll
        for (int nb = 0; nb < 4; ++nb) {
            const int col0 = cg * 32 + nb * 8 + 2 * tc;
            const float2 bi = *reinterpret_cast<const float2*>(sB2a + col0);
            *reinterpret_cast<float2*>(sH + tg * 68 + col0) =
                make_float2(fmaxf(acc[nb][0] + bi.x, 0.0f), fmaxf(acc[nb][1] + bi.y, 0.0f));
            *reinterpret_cast<float2*>(sH + (tg + 8) * 68 + col0) =
                make_float2(fmaxf(acc[nb][2] + bi.x, 0.0f), fmaxf(acc[nb][3] + bi.y, 0.0f));
        }
        barp(pr + 1);

        float acc2[4][4];
        gemm<8>(sH, 68, sW2b, tg, tc, lane, cg, acc2);

#pragma unroll
        for (int nb = 0; nb < 4; ++nb) {
            const int col0 = cg * 32 + nb * 8 + 2 * tc;
            const float2 bi = *reinterpret_cast<const float2*>(sB2b + col0);
            *reinterpret_cast<float2*>(outp + (size_t)(base + tg) * 64 + col0) =
                make_float2(acc2[nb][0] + bi.x, acc2[nb][1] + bi.y);
            *reinterpret_cast<float2*>(outp + (size_t)(base + tg + 8) * 64 + col0) =
                make_float2(acc2[nb][2] + bi.x, acc2[nb][3] + bi.y);
        }
        barp(pr + 1);
    }
}

// ---------------- launch ----------------------------------------------------------------
extern "C" void kernel_launch(void* const* d_in, const int* in_sizes, int n_in,
                              void* d_out, int out_size) {
    const float* x   = reinterpret_cast<const float*>(d_in[0]);
    const void*  ei  = d_in[1];
    const float* ea  = reinterpret_cast<const float*>(d_in[2]);
    const float* W1a = reinterpret_cast<const float*>(d_in[5]);
    const float* b1a = reinterpret_cast<const float*>(d_in[6]);
    const float* W1b = reinterpret_cast<const float*>(d_in[7]);
    const float* b1b = reinterpret_cast<const float*>(d_in[8]);
    const float* W2a = reinterpret_cast<const float*>(d_in[9]);
    const float* b2a = reinterpret_cast<const float*>(d_in[10]);
    const float* W2b = reinterpret_cast<const float*>(d_in[11]);
    const float* b2b = reinterpret_cast<const float*>(d_in[12]);
    float* out = reinterpret_cast<float*>(d_out);

    cudaFuncSetAttribute(p_pass,    cudaFuncAttributeMaxDynamicSharedMemorySize, P_SMEM_B);
    cudaFuncSetAttribute(edge_pass, cudaFuncAttributeMaxDynamicSharedMemorySize, E_SMEM_B);
    cudaFuncSetAttribute(node_pass, cudaFuncAttributeMaxDynamicSharedMemorySize, N_SMEM_B);

    p_pass<<<148, PNT, P_SMEM_B>>>(x, W1a);                    // zeros scratch + P
    edge_pass<<<148, ENT, E_SMEM_B>>>(ei, ea, W1a + 64 * 64, b1a);
    node_pass<<<148, NNT, N_SMEM_B>>>(x, W1b, b1b, W2a, b2a, W2b, b2b, out);
}